// round 16
// baseline (speedup 1.0000x reference)
#include <cuda_runtime.h>
#include <cuda_fp16.h>
#include <cstdint>

#define NMAX  100000
#define EMAX  1600000
#define PREP_BLOCKS 256
#define PREP_THREADS 512

// ---------------------------------------------------------------- scratch
__device__ float    g_dis[NMAX];
__device__ int      g_deg [NMAX];
__device__ int      g_rowptr[NMAX + 1];
__device__ int      g_cursor[NMAX];
__device__ int      g_esrc[EMAX];
__device__ uint32_t g_t16[NMAX * 64];      // half2 activations buffer A
__device__ uint32_t g_a16[NMAX * 64];      // fp16 x (k-permuted) for GEMM1
__device__ uint32_t g_b16[NMAX * 64];      // half2 activations buffer B
__device__ uint32_t g_w16[4][8192];        // fp16 W^T images (single plane)
__device__ float    g_bc[128];             // b_emb @ W1
__device__ int      g_bsum[PREP_BLOCKS];
__device__ int      g_boff[PREP_BLOCKS];
__device__ int      g_total;
__device__ unsigned g_bar;

// ---------------------------------------------------------------- helpers
__device__ __forceinline__ uint32_t sm32(const void* p) {
    uint32_t a;
    asm("{ .reg .u64 t; cvta.to.shared.u64 t, %1; cvt.u32.u64 %0, t; }" : "=r"(a) : "l"(p));
    return a;
}
__device__ __forceinline__ void cpa16(uint32_t dst, const void* src) {
    asm volatile("cp.async.cg.shared.global [%0], [%1], 16;" :: "r"(dst), "l"(src));
}
__device__ __forceinline__ uint32_t packh2(float v0, float v1) {
    __half2 h = __floats2half2_rn(v0, v1);
    return *reinterpret_cast<uint32_t*>(&h);
}
__device__ __forceinline__ float2 unph2(uint32_t u) {
    return __half22float2(*reinterpret_cast<__half2*>(&u));
}
// k-pair permuted uint index within a 64-uint (128 half) row, m = k-pair index 0..63
__device__ __forceinline__ int widx(int m) {
    int mg = m & 7;
    return ((m >> 3) << 3) + ((mg & 3) << 1) + (mg >> 2);
}
#define MMA_F16(d, a, b) \
    asm volatile("mma.sync.aligned.m16n8k16.row.col.f32.f16.f16.f32 " \
        "{%0,%1,%2,%3}, {%4,%5,%6,%7}, {%8,%9}, {%0,%1,%2,%3};" \
        : "+f"((d)[0]), "+f"((d)[1]), "+f"((d)[2]), "+f"((d)[3]) \
        : "r"((a)[0]), "r"((a)[1]), "r"((a)[2]), "r"((a)[3]), "r"((b).x), "r"((b).y))

// ---------------------------------------------------------------- grid sync
__device__ __forceinline__ void grid_sync(int nb) {
    __syncthreads();
    if (threadIdx.x == 0) {
        __threadfence();
        unsigned ticket = atomicAdd(&g_bar, 1u);
        unsigned phase  = ticket / (unsigned)nb + 1u;
        while (atomicAdd(&g_bar, 0u) < phase * (unsigned)nb) { }
    }
    __syncthreads();
}

// ---------------------------------------------------------------- fused prep
__global__ __launch_bounds__(PREP_THREADS, 1)
void k_prep(const int* __restrict__ src, const int* __restrict__ dst, int e, int n,
            float* __restrict__ d_out, int out4,
            const float* __restrict__ x, const float* __restrict__ We,
            const float* __restrict__ W1, const float* __restrict__ W2,
            const float* __restrict__ W3, const float* __restrict__ be,
            uint32_t* __restrict__ a16) {
    const int tid  = threadIdx.x;
    const int lane = tid & 31, wid = tid >> 5;
    const int T    = PREP_BLOCKS * PREP_THREADS;
    const int gtid = blockIdx.x * PREP_THREADS + tid;
    const bool vec4 = (e & 3) == 0;
    __shared__ int sh[32];
    __shared__ int s_boff;

    for (int i = gtid; i < n; i += T) g_deg[i] = 0;
    grid_sync(PREP_BLOCKS);

    // histogram (4-wide) + independent prologue work
    if (vec4) {
        const int4* d4 = reinterpret_cast<const int4*>(dst);
        const int e4 = e >> 2;
        for (int i = gtid; i < e4; i += T) {
            int4 d = __ldg(&d4[i]);
            atomicAdd(&g_deg[d.x], 1);
            atomicAdd(&g_deg[d.y], 1);
            atomicAdd(&g_deg[d.z], 1);
            atomicAdd(&g_deg[d.w], 1);
        }
    } else {
        for (int i = gtid; i < e; i += T) atomicAdd(&g_deg[dst[i]], 1);
    }

    for (int i = gtid; i < n * 64; i += T) {
        int node = i >> 6, m = i & 63;
        float2 v = *reinterpret_cast<const float2*>(&x[(size_t)node * 128 + m * 2]);
        a16[(size_t)node * 64 + widx(m)] = packh2(v.x, v.y);
    }
    for (int i = gtid; i < 2 * 8192; i += T) {
        int L = 2 + (i >> 13);
        int idx = i & 8191;
        int N = (L == 3) ? 64 : 128;
        int nn = idx >> 6, m = idx & 63;
        if (nn < N) {
            const float* W = (L == 2) ? W2 : W3;
            float v0 = W[(size_t)(2 * m) * N + nn];
            float v1 = W[(size_t)(2 * m + 1) * N + nn];
            g_w16[L][nn * 64 + widx(m)] = packh2(v0, v1);
        }
    }
    if ((gtid & 15) == 0) {
        int j = gtid >> 4;
        if (j < 8192) {
            int m = j >> 7, nn = j & 127;
            float v0 = 0.f, v1 = 0.f;
            const float* r0 = &We[(size_t)(2 * m) * 128];
            const float* r1 = &We[(size_t)(2 * m + 1) * 128];
#pragma unroll 4
            for (int k = 0; k < 128; k++) {
                float w = W1[(size_t)k * 128 + nn];
                v0 = fmaf(r0[k], w, v0);
                v1 = fmaf(r1[k], w, v1);
            }
            g_w16[0][nn * 64 + widx(m)] = packh2(v0, v1);
        }
        if (j < 128) {
            float b = 0.f;
            for (int k = 0; k < 128; k++) b = fmaf(be[k], W1[(size_t)k * 128 + j], b);
            g_bc[j] = b;
        }
    }
    float4* o4 = reinterpret_cast<float4*>(d_out);
    for (int i = gtid; i < out4; i += T) o4[i] = make_float4(0.f, 0.f, 0.f, 0.f);
    grid_sync(PREP_BLOCKS);

    for (int i = gtid; i < n; i += T) g_dis[i] = rsqrtf((float)g_deg[i] + 1.0f);

    const int per = (n + T - 1) / T;
    const int cb  = gtid * per;
    const int ce  = min(cb + per, n);
    int csum = 0;
    for (int i = cb; i < ce; i++) csum += g_deg[i];

    if (tid < 32) sh[tid] = 0;
    __syncthreads();

    int x0 = csum;
#pragma unroll
    for (int o = 1; o < 32; o <<= 1) {
        int y = __shfl_up_sync(0xffffffffu, x0, o);
        if (lane >= o) x0 += y;
    }
    if (lane == 31) sh[wid] = x0;
    __syncthreads();
    if (wid == 0) {
        int w = sh[lane];
        int xx = w;
#pragma unroll
        for (int o = 1; o < 32; o <<= 1) {
            int y = __shfl_up_sync(0xffffffffu, xx, o);
            if (lane >= o) xx += y;
        }
        sh[lane] = xx - w;
        if (lane == 31) g_bsum[blockIdx.x] = xx;
    }
    __syncthreads();
    const int thr_excl = x0 - csum + sh[wid];
    grid_sync(PREP_BLOCKS);

    if (blockIdx.x == 0 && wid == 0) {
        int carry = 0;
        for (int base = 0; base < PREP_BLOCKS; base += 32) {
            int v = g_bsum[base + lane];
            int s = v;
#pragma unroll
            for (int o = 1; o < 32; o <<= 1) {
                int y = __shfl_up_sync(0xffffffffu, s, o);
                if (lane >= o) s += y;
            }
            g_boff[base + lane] = s - v + carry;
            carry += __shfl_sync(0xffffffffu, s, 31);
        }
        if (lane == 0) g_total = carry;
    }
    grid_sync(PREP_BLOCKS);

    if (tid == 0) s_boff = g_boff[blockIdx.x];
    __syncthreads();
    int run = s_boff + thr_excl;
    for (int i = cb; i < ce; i++) {
        g_rowptr[i] = run;
        g_cursor[i] = run;
        run += g_deg[i];
    }
    if (gtid == 0) g_rowptr[n] = g_total;
    grid_sync(PREP_BLOCKS);

    if (vec4) {
        const int4* d4 = reinterpret_cast<const int4*>(dst);
        const int4* s4 = reinterpret_cast<const int4*>(src);
        const int e4 = e >> 2;
        for (int i = gtid; i < e4; i += T) {
            int4 d = __ldg(&d4[i]);
            int4 s = __ldg(&s4[i]);
            int p0 = atomicAdd(&g_cursor[d.x], 1);
            int p1 = atomicAdd(&g_cursor[d.y], 1);
            int p2 = atomicAdd(&g_cursor[d.z], 1);
            int p3 = atomicAdd(&g_cursor[d.w], 1);
            g_esrc[p0] = s.x;
            g_esrc[p1] = s.y;
            g_esrc[p2] = s.z;
            g_esrc[p3] = s.w;
        }
    } else {
        for (int i = gtid; i < e; i += T) {
            int pos = atomicAdd(&g_cursor[dst[i]], 1);
            g_esrc[pos] = src[i];
        }
    }
}

// ---------------------------------------------------------------- mma GEMM (standalone, layer 1)
template <int BN, bool SCALE, bool BIAS>
__global__ void __launch_bounds__(256, 2)
k_mgemm(const uint32_t* __restrict__ A16, const uint32_t* __restrict__ W16,
        const float* __restrict__ bias, const float* __restrict__ dis,
        uint32_t* __restrict__ out16, int M)
{
    constexpr int NT = BN / 16;
    __shared__ __align__(16) uint32_t sA[3][128 * 8];
    __shared__ __align__(16) uint32_t sW[3][BN * 8];

    const int tid  = threadIdx.x;
    const int wid  = tid >> 5, lane = tid & 31;
    const int g    = lane >> 2, t = lane & 3;
    const int wm   = wid & 3, wn = wid >> 2;
    const int row0 = blockIdx.x * 128;

    const uint32_t sAb = sm32(sA);
    const uint32_t sWb = sm32(sW);
    constexpr uint32_t A_P = 128 * 8 * 4;
    constexpr uint32_t W_P = BN * 8 * 4;

    float acc[2][NT][4];
#pragma unroll
    for (int i = 0; i < 2; i++)
#pragma unroll
        for (int j = 0; j < NT; j++)
#pragma unroll
            for (int q = 0; q < 4; q++) acc[i][j][q] = 0.f;

    auto issue = [&](int kt, int buf) {
        int r = tid >> 1, h = tid & 1;
        int gr = row0 + r; if (gr >= M) gr = M - 1;
        uint32_t off = (uint32_t)(r * 8 + h * 4) * 4u;
        cpa16(sAb + (uint32_t)buf * A_P + off, A16 + (size_t)gr * 64 + kt * 8 + h * 4);
        if (tid < BN * 2) {
            cpa16(sWb + (uint32_t)buf * W_P + off, W16 + r * 64 + kt * 8 + h * 4);
        }
        asm volatile("cp.async.commit_group;" ::: "memory");
    };

    issue(0, 0);
    issue(1, 1);
    for (int kt = 0; kt < 8; kt++) {
        const int buf = kt % 3;
        if (kt < 6) {
            issue(kt + 2, (kt + 2) % 3);
            asm volatile("cp.async.wait_group 2;" ::: "memory");
        } else if (kt == 6) {
            asm volatile("cp.async.wait_group 1;" ::: "memory");
        } else {
            asm volatile("cp.async.wait_group 0;" ::: "memory");
        }
        __syncthreads();

        const uint32_t* pA = sA[buf];
        const uint32_t* pW = sW[buf];

        uint32_t a[2][4];
#pragma unroll
        for (int mt = 0; mt < 2; mt++) {
            int r0 = wm * 32 + mt * 16 + g;
            uint2 v;
            v = *reinterpret_cast<const uint2*>(&pA[r0 * 8 + t * 2]);
            a[mt][0] = v.x; a[mt][2] = v.y;
            v = *reinterpret_cast<const uint2*>(&pA[(r0 + 8) * 8 + t * 2]);
            a[mt][1] = v.x; a[mt][3] = v.y;
        }
#pragma unroll
        for (int nt = 0; nt < NT; nt++) {
            int rn = wn * (NT * 8) + nt * 8 + g;
            uint2 bw = *reinterpret_cast<const uint2*>(&pW[rn * 8 + t * 2]);
#pragma unroll
            for (int mt = 0; mt < 2; mt++) {
                MMA_F16(acc[mt][nt], a[mt], bw);
            }
        }
        __syncthreads();
    }

#pragma unroll
    for (int mt = 0; mt < 2; mt++) {
        int r0 = row0 + wm * 32 + mt * 16 + g;
        int r1 = r0 + 8;
        bool ok0 = r0 < M, ok1 = r1 < M;
        float sc0 = (SCALE && ok0) ? dis[r0] : 1.0f;
        float sc1 = (SCALE && ok1) ? dis[r1] : 1.0f;
#pragma unroll
        for (int nt = 0; nt < NT; nt++) {
            int c = wn * (NT * 8) + nt * 8 + 2 * t;
            float b0 = 0.f, b1 = 0.f;
            if (BIAS) {
                float2 bb = *reinterpret_cast<const float2*>(&bias[c]);
                b0 = bb.x; b1 = bb.y;
            }
            float v00 = (acc[mt][nt][0] + b0) * sc0;
            float v01 = (acc[mt][nt][1] + b1) * sc0;
            float v10 = (acc[mt][nt][2] + b0) * sc1;
            float v11 = (acc[mt][nt][3] + b1) * sc1;
            if (ok0) out16[(size_t)r0 * (BN / 2) + (c >> 1)] = packh2(v00, v01);
            if (ok1) out16[(size_t)r1 * (BN / 2) + (c >> 1)] = packh2(v10, v11);
        }
    }
}

// ---------------------------------------------------------------- fused agg + GEMM
// Phase A: each warp aggregates 16 of the block's 128 nodes from tin (rows of 64
// uints, half2), applies dis/bias/relu, writes fp16 rows into smem A planes
// (k-permuted, same layout the mma fragments read).
// Phase B: t_out = fp16( (A @ W) * dis ), A resident in smem, W 3-stage cp.async.
template <int BN>
__global__ void __launch_bounds__(256, 2)
k_fused(const uint32_t* __restrict__ tin, const int* __restrict__ rowptr,
        const int* __restrict__ esrc, const float* __restrict__ dis,
        const float* __restrict__ biasA, const uint32_t* __restrict__ W16,
        uint32_t* __restrict__ out16, int M)
{
    constexpr int NT = BN / 16;
    __shared__ __align__(16) uint32_t sA[8][128 * 8];   // 32 KB, full A tile
    __shared__ __align__(16) uint32_t sW[3][BN * 8];

    const int tid  = threadIdx.x;
    const int wid  = tid >> 5, lane = tid & 31;
    const int g    = lane >> 2, t = lane & 3;
    const int wm   = wid & 3, wn = wid >> 2;
    const int row0 = blockIdx.x * 128;

    const uint32_t sWb = sm32(sW);
    constexpr uint32_t W_P = BN * 8 * 4;

    auto issueW = [&](int kt, int buf) {
        if (tid < BN * 2) {
            int r = tid >> 1, h = tid & 1;
            uint32_t off = (uint32_t)(r * 8 + h * 4) * 4u;
            cpa16(sWb + (uint32_t)buf * W_P + off, W16 + r * 64 + kt * 8 + h * 4);
        }
        asm volatile("cp.async.commit_group;" ::: "memory");
    };

    // start W prefetch before the gather so it overlaps phase A
    issueW(0, 0);
    issueW(1, 1);

    // ---- phase A: aggregate this block's 128 rows into smem ----
    {
        const int kt   = lane >> 2;                 // plane for this lane's pair
        const int off0 = widx(lane * 2) & 7;
        const int off1 = widx(lane * 2 + 1) & 7;
        float4 b = *reinterpret_cast<const float4*>(&biasA[lane * 4]);
        for (int i = 0; i < 16; i++) {
            int r  = wid * 16 + i;
            int gr = row0 + r; if (gr >= M) gr = M - 1;
            int beg = __ldg(&rowptr[gr]);
            int end = __ldg(&rowptr[gr + 1]);
            uint2 sv = *reinterpret_cast<const uint2*>(&tin[(size_t)gr * 64 + lane * 2]);
            float2 a0 = unph2(sv.x), a1 = unph2(sv.y);
            float4 acc = make_float4(a0.x, a0.y, a1.x, a1.y);
            int e = beg;
            for (; e + 8 <= end; e += 8) {
                int s[8];
#pragma unroll
                for (int u = 0; u < 8; u++) s[u] = __ldg(&esrc[e + u]);
                uint2 v[8];
#pragma unroll
                for (int u = 0; u < 8; u++)
                    v[u] = *reinterpret_cast<const uint2*>(&tin[(size_t)s[u] * 64 + lane * 2]);
#pragma unroll
                for (int u = 0; u < 8; u++) {
                    float2 f0 = unph2(v[u].x), f1 = unph2(v[u].y);
                    acc.x += f0.x; acc.y += f0.y; acc.z += f1.x; acc.w += f1.y;
                }
            }
            for (; e < end; e++) {
                int s = __ldg(&esrc[e]);
                uint2 v = *reinterpret_cast<const uint2*>(&tin[(size_t)s * 64 + lane * 2]);
                float2 f0 = unph2(v.x), f1 = unph2(v.y);
                acc.x += f0.x; acc.y += f0.y; acc.z += f1.x; acc.w += f1.y;
            }
            float d = dis[gr];
            float rx = fmaxf(fmaf(acc.x, d, b.x), 0.f);
            float ry = fmaxf(fmaf(acc.y, d, b.y), 0.f);
            float rz = fmaxf(fmaf(acc.z, d, b.z), 0.f);
            float rw = fmaxf(fmaf(acc.w, d, b.w), 0.f);
            sA[kt][r * 8 + off0] = packh2(rx, ry);
            sA[kt][r * 8 + off1] = packh2(rz, rw);
        }
    }
    __syncthreads();

    // ---- phase B: mma ----
    float acc[2][NT][4];
#pragma unroll
    for (int i = 0; i < 2; i++)
#pragma unroll
        for (int j = 0; j < NT; j++)
#pragma unroll
            for (int q = 0; q < 4; q++) acc[i][j][q] = 0.f;

    for (int kt = 0; kt < 8; kt++) {
        const int buf = kt % 3;
        if (kt < 6) {
            issueW(kt + 2, (kt + 2) % 3);
            asm volatile("cp.async.wait_group 2;" ::: "memory");
        } else if (kt == 6) {
            asm volatile("cp.async.wait_group 1;" ::: "memory");
        } else {
            asm volatile("cp.async.wait_group 0;" ::: "memory");
        }
        __syncthreads();

        const uint32_t* pA = sA[kt];
        const uint32_t* pW = sW[buf];

        uint32_t a[2][4];
#pragma unroll
        for (int mt = 0; mt < 2; mt++) {
            int r0 = wm * 32 + mt * 16 + g;
            uint2 v;
            v = *reinterpret_cast<const uint2*>(&pA[r0 * 8 + t * 2]);
            a[mt][0] = v.x; a[mt][2] = v.y;
            v = *reinterpret_cast<const uint2*>(&pA[(r0 + 8) * 8 + t * 2]);
            a[mt][1] = v.x; a[mt][3] = v.y;
        }
#pragma unroll
        for (int nt = 0; nt < NT; nt++) {
            int rn = wn * (NT * 8) + nt * 8 + g;
            uint2 bw = *reinterpret_cast<const uint2*>(&pW[rn * 8 + t * 2]);
#pragma unroll
            for (int mt = 0; mt < 2; mt++) {
                MMA_F16(acc[mt][nt], a[mt], bw);
            }
        }
        __syncthreads();
    }

    // ---- epilogue: v = acc * dis ----
#pragma unroll
    for (int mt = 0; mt < 2; mt++) {
        int r0 = row0 + wm * 32 + mt * 16 + g;
        int r1 = r0 + 8;
        bool ok0 = r0 < M, ok1 = r1 < M;
        float sc0 = ok0 ? dis[r0] : 1.0f;
        float sc1 = ok1 ? dis[r1] : 1.0f;
#pragma unroll
        for (int nt = 0; nt < NT; nt++) {
            int c = wn * (NT * 8) + nt * 8 + 2 * t;
            float v00 = acc[mt][nt][0] * sc0;
            float v01 = acc[mt][nt][1] * sc0;
            float v10 = acc[mt][nt][2] * sc1;
            float v11 = acc[mt][nt][3] * sc1;
            if (ok0) out16[(size_t)r0 * (BN / 2) + (c >> 1)] = packh2(v00, v01);
            if (ok1) out16[(size_t)r1 * (BN / 2) + (c >> 1)] = packh2(v10, v11);
        }
    }
}

// ---------------------------------------------------------------- final agg + pool
__global__ void k_aggpool(const uint32_t* __restrict__ tb16, const int* __restrict__ rowptr,
                          const int* __restrict__ esrc, const float* __restrict__ dis,
                          const float* __restrict__ bias, const int* __restrict__ batch,
                          float* __restrict__ dout, int n) {
    const int warp = (blockIdx.x * blockDim.x + threadIdx.x) >> 5;
    const int lane = threadIdx.x & 31;
    if (warp >= n) return;
    const int beg = __ldg(&rowptr[warp]);
    const int end = __ldg(&rowptr[warp + 1]);

    float2 acc = unph2(tb16[(size_t)warp * 32 + lane]);
    int e = beg;
    for (; e + 8 <= end; e += 8) {
        int s[8];
#pragma unroll
        for (int u = 0; u < 8; u++) s[u] = __ldg(&esrc[e + u]);
        uint32_t v[8];
#pragma unroll
        for (int u = 0; u < 8; u++) v[u] = tb16[(size_t)s[u] * 32 + lane];
#pragma unroll
        for (int u = 0; u < 8; u++) {
            float2 f = unph2(v[u]);
            acc.x += f.x; acc.y += f.y;
        }
    }
    for (; e < end; e++) {
        int s = __ldg(&esrc[e]);
        float2 f = unph2(tb16[(size_t)s * 32 + lane]);
        acc.x += f.x; acc.y += f.y;
    }
    float d = dis[warp];
    float2 b = *reinterpret_cast<const float2*>(&bias[lane * 2]);
    float rx = fmaf(acc.x, d, b.x);
    float ry = fmaf(acc.y, d, b.y);
    int gidx = __ldg(&batch[warp]);
    float* a = &dout[(size_t)gidx * 64 + lane * 2];
    asm volatile("red.global.add.v2.f32 [%0], {%1,%2};"
                 :: "l"(a), "f"(rx), "f"(ry) : "memory");
}

// ---------------------------------------------------------------- launch
extern "C" void kernel_launch(void* const* d_in, const int* in_sizes, int n_in,
                              void* d_out, int out_size) {
    const float* x     = (const float*)d_in[0];
    const int*   ei    = (const int*)  d_in[1];
    const int*   batch = (const int*)  d_in[2];
    const float* W_emb = (const float*)d_in[3];
    const float* b_emb = (const float*)d_in[4];
    const float* W1    = (const float*)d_in[5];
    const float* b1    = (const float*)d_in[6];
    const float* W2    = (const float*)d_in[7];
    const float* b2    = (const float*)d_in[8];
    const float* W3    = (const float*)d_in[9];
    const float* b3    = (const float*)d_in[10];

    const int n = in_sizes[2];
    const int e = in_sizes[1] / 2;
    const int* src = ei;
    const int* dst = ei + e;

    float *dis, *bc;
    int *rowptr, *esrc;
    uint32_t *t16, *a16, *b16, *w16;
    cudaGetSymbolAddress((void**)&dis,    g_dis);
    cudaGetSymbolAddress((void**)&bc,     g_bc);
    cudaGetSymbolAddress((void**)&rowptr, g_rowptr);
    cudaGetSymbolAddress((void**)&esrc,   g_esrc);
    cudaGetSymbolAddress((void**)&t16,    g_t16);
    cudaGetSymbolAddress((void**)&a16,    g_a16);
    cudaGetSymbolAddress((void**)&b16,    g_b16);
    cudaGetSymbolAddress((void**)&w16,    g_w16);

    auto cdiv = [](long long a, long long b) { return (int)((a + b - 1) / b); };

    // 0: fused prep (CSR + dis + weight images + Wc/bc + xconv + zero d_out)
    k_prep<<<PREP_BLOCKS, PREP_THREADS>>>(src, dst, e, n, (float*)d_out, out_size / 4,
                                          x, W_emb, W1, W2, W3, b_emb, a16);
    // 1: layer-1 GEMM (folded embedding)  t16 = fp16((x@Wc + bc) * dis)
    k_mgemm<128, true, true><<<cdiv(n, 128), 256>>>(
        a16, w16 + 0 * 8192, bc, dis, t16, n);
    // 2: fused layer-1 agg + layer-2 GEMM:  b16 = fp16((relu(agg(t16)+b1) @ W2) * dis)
    k_fused<128><<<cdiv(n, 128), 256>>>(t16, rowptr, esrc, dis, b1,
                                        w16 + 2 * 8192, b16, n);
    // 3: fused layer-2 agg + layer-3 GEMM:  t16 = fp16((relu(agg(b16)+b2) @ W3) * dis)
    k_fused<64><<<cdiv(n, 128), 256>>>(b16, rowptr, esrc, dis, b2,
                                       w16 + 3 * 8192, t16, n);
    // 4: layer-3 agg + pool
    k_aggpool<<<cdiv(n, 8), 256>>>(t16, rowptr, esrc, dis, b3, batch, (float*)d_out, n);
}

// round 17
// speedup vs baseline: 1.2461x; 1.2461x over previous
#include <cuda_runtime.h>
#include <cuda_fp16.h>
#include <cstdint>

#define NMAX  100000
#define EMAX  1600000
#define PREP_BLOCKS 256
#define PREP_THREADS 512

// ---------------------------------------------------------------- scratch
__device__ float    g_dis[NMAX];
__device__ int      g_deg [NMAX];
__device__ int      g_rowptr[NMAX + 1];
__device__ int      g_cursor[NMAX];
__device__ int      g_esrc[EMAX];
__device__ uint32_t g_t16[NMAX * 64];      // half2 activations (GEMM out / agg in)
__device__ uint32_t g_a16[NMAX * 64];      // fp16 activations (k-permuted)
__device__ uint32_t g_b16[NMAX * 64];      // fp16 activations (k-permuted)
__device__ uint32_t g_w16[4][8192];        // fp16 W^T images (single plane)
__device__ float    g_bc[128];             // b_emb @ W1
__device__ int      g_bsum[PREP_BLOCKS];
__device__ int      g_boff[PREP_BLOCKS];
__device__ int      g_total;
__device__ unsigned g_bar;

// ---------------------------------------------------------------- helpers
__device__ __forceinline__ uint32_t sm32(const void* p) {
    uint32_t a;
    asm("{ .reg .u64 t; cvta.to.shared.u64 t, %1; cvt.u32.u64 %0, t; }" : "=r"(a) : "l"(p));
    return a;
}
__device__ __forceinline__ void cpa16(uint32_t dst, const void* src) {
    asm volatile("cp.async.cg.shared.global [%0], [%1], 16;" :: "r"(dst), "l"(src));
}
__device__ __forceinline__ uint32_t packh2(float v0, float v1) {
    __half2 h = __floats2half2_rn(v0, v1);
    return *reinterpret_cast<uint32_t*>(&h);
}
__device__ __forceinline__ float2 unph2(uint32_t u) {
    return __half22float2(*reinterpret_cast<__half2*>(&u));
}
// k-pair permuted uint index within a 64-uint (128 half) row, m = k-pair index 0..63
__device__ __forceinline__ int widx(int m) {
    int mg = m & 7;
    return ((m >> 3) << 3) + ((mg & 3) << 1) + (mg >> 2);
}
#define MMA_F16(d, a, b) \
    asm volatile("mma.sync.aligned.m16n8k16.row.col.f32.f16.f16.f32 " \
        "{%0,%1,%2,%3}, {%4,%5,%6,%7}, {%8,%9}, {%0,%1,%2,%3};" \
        : "+f"((d)[0]), "+f"((d)[1]), "+f"((d)[2]), "+f"((d)[3]) \
        : "r"((a)[0]), "r"((a)[1]), "r"((a)[2]), "r"((a)[3]), "r"((b).x), "r"((b).y))

// ---------------------------------------------------------------- grid sync
__device__ __forceinline__ void grid_sync(int nb) {
    __syncthreads();
    if (threadIdx.x == 0) {
        __threadfence();
        unsigned ticket = atomicAdd(&g_bar, 1u);
        unsigned phase  = ticket / (unsigned)nb + 1u;
        while (atomicAdd(&g_bar, 0u) < phase * (unsigned)nb) { }
    }
    __syncthreads();
}

// ---------------------------------------------------------------- fused prep
__global__ __launch_bounds__(PREP_THREADS, 1)
void k_prep(const int* __restrict__ src, const int* __restrict__ dst, int e, int n,
            float* __restrict__ d_out, int out4,
            const float* __restrict__ x, const float* __restrict__ We,
            const float* __restrict__ W1, const float* __restrict__ W2,
            const float* __restrict__ W3, const float* __restrict__ be,
            uint32_t* __restrict__ a16) {
    const int tid  = threadIdx.x;
    const int lane = tid & 31, wid = tid >> 5;
    const int T    = PREP_BLOCKS * PREP_THREADS;
    const int gtid = blockIdx.x * PREP_THREADS + tid;
    const bool vec4 = (e & 3) == 0;
    __shared__ int sh[32];
    __shared__ int s_boff;

    for (int i = gtid; i < n; i += T) g_deg[i] = 0;
    grid_sync(PREP_BLOCKS);

    // histogram (4-wide) + independent prologue work
    if (vec4) {
        const int4* d4 = reinterpret_cast<const int4*>(dst);
        const int e4 = e >> 2;
        for (int i = gtid; i < e4; i += T) {
            int4 d = __ldg(&d4[i]);
            atomicAdd(&g_deg[d.x], 1);
            atomicAdd(&g_deg[d.y], 1);
            atomicAdd(&g_deg[d.z], 1);
            atomicAdd(&g_deg[d.w], 1);
        }
    } else {
        for (int i = gtid; i < e; i += T) atomicAdd(&g_deg[dst[i]], 1);
    }

    for (int i = gtid; i < n * 64; i += T) {
        int node = i >> 6, m = i & 63;
        float2 v = *reinterpret_cast<const float2*>(&x[(size_t)node * 128 + m * 2]);
        a16[(size_t)node * 64 + widx(m)] = packh2(v.x, v.y);
    }
    for (int i = gtid; i < 2 * 8192; i += T) {
        int L = 2 + (i >> 13);
        int idx = i & 8191;
        int N = (L == 3) ? 64 : 128;
        int nn = idx >> 6, m = idx & 63;
        if (nn < N) {
            const float* W = (L == 2) ? W2 : W3;
            float v0 = W[(size_t)(2 * m) * N + nn];
            float v1 = W[(size_t)(2 * m + 1) * N + nn];
            g_w16[L][nn * 64 + widx(m)] = packh2(v0, v1);
        }
    }
    if ((gtid & 15) == 0) {
        int j = gtid >> 4;
        if (j < 8192) {
            int m = j >> 7, nn = j & 127;
            float v0 = 0.f, v1 = 0.f;
            const float* r0 = &We[(size_t)(2 * m) * 128];
            const float* r1 = &We[(size_t)(2 * m + 1) * 128];
#pragma unroll 4
            for (int k = 0; k < 128; k++) {
                float w = W1[(size_t)k * 128 + nn];
                v0 = fmaf(r0[k], w, v0);
                v1 = fmaf(r1[k], w, v1);
            }
            g_w16[0][nn * 64 + widx(m)] = packh2(v0, v1);
        }
        if (j < 128) {
            float b = 0.f;
            for (int k = 0; k < 128; k++) b = fmaf(be[k], W1[(size_t)k * 128 + j], b);
            g_bc[j] = b;
        }
    }
    float4* o4 = reinterpret_cast<float4*>(d_out);
    for (int i = gtid; i < out4; i += T) o4[i] = make_float4(0.f, 0.f, 0.f, 0.f);
    grid_sync(PREP_BLOCKS);

    for (int i = gtid; i < n; i += T) g_dis[i] = rsqrtf((float)g_deg[i] + 1.0f);

    const int per = (n + T - 1) / T;
    const int cb  = gtid * per;
    const int ce  = min(cb + per, n);
    int csum = 0;
    for (int i = cb; i < ce; i++) csum += g_deg[i];

    if (tid < 32) sh[tid] = 0;
    __syncthreads();

    int x0 = csum;
#pragma unroll
    for (int o = 1; o < 32; o <<= 1) {
        int y = __shfl_up_sync(0xffffffffu, x0, o);
        if (lane >= o) x0 += y;
    }
    if (lane == 31) sh[wid] = x0;
    __syncthreads();
    if (wid == 0) {
        int w = sh[lane];
        int xx = w;
#pragma unroll
        for (int o = 1; o < 32; o <<= 1) {
            int y = __shfl_up_sync(0xffffffffu, xx, o);
            if (lane >= o) xx += y;
        }
        sh[lane] = xx - w;
        if (lane == 31) g_bsum[blockIdx.x] = xx;
    }
    __syncthreads();
    const int thr_excl = x0 - csum + sh[wid];
    grid_sync(PREP_BLOCKS);

    if (blockIdx.x == 0 && wid == 0) {
        int carry = 0;
        for (int base = 0; base < PREP_BLOCKS; base += 32) {
            int v = g_bsum[base + lane];
            int s = v;
#pragma unroll
            for (int o = 1; o < 32; o <<= 1) {
                int y = __shfl_up_sync(0xffffffffu, s, o);
                if (lane >= o) s += y;
            }
            g_boff[base + lane] = s - v + carry;
            carry += __shfl_sync(0xffffffffu, s, 31);
        }
        if (lane == 0) g_total = carry;
    }
    grid_sync(PREP_BLOCKS);

    if (tid == 0) s_boff = g_boff[blockIdx.x];
    __syncthreads();
    int run = s_boff + thr_excl;
    for (int i = cb; i < ce; i++) {
        g_rowptr[i] = run;
        g_cursor[i] = run;
        run += g_deg[i];
    }
    if (gtid == 0) g_rowptr[n] = g_total;
    grid_sync(PREP_BLOCKS);

    if (vec4) {
        const int4* d4 = reinterpret_cast<const int4*>(dst);
        const int4* s4 = reinterpret_cast<const int4*>(src);
        const int e4 = e >> 2;
        for (int i = gtid; i < e4; i += T) {
            int4 d = __ldg(&d4[i]);
            int4 s = __ldg(&s4[i]);
            int p0 = atomicAdd(&g_cursor[d.x], 1);
            int p1 = atomicAdd(&g_cursor[d.y], 1);
            int p2 = atomicAdd(&g_cursor[d.z], 1);
            int p3 = atomicAdd(&g_cursor[d.w], 1);
            g_esrc[p0] = s.x;
            g_esrc[p1] = s.y;
            g_esrc[p2] = s.z;
            g_esrc[p3] = s.w;
        }
    } else {
        for (int i = gtid; i < e; i += T) {
            int pos = atomicAdd(&g_cursor[dst[i]], 1);
            g_esrc[pos] = src[i];
        }
    }
}

// ---------------------------------------------------------------- mma GEMM
// t16[M,BN] = fp16( (A[M,128] @ W[128,BN] + bias) * dis[row] )
// BM=128, 8 warps as 4(m) x 2(n). A/W fp16 single plane (k-permuted).
// 4-buffer cp.async ring, ONE __syncthreads per k-tile (issue after barrier).
template <int BN, bool SCALE, bool BIAS>
__global__ void __launch_bounds__(256, 2)
k_mgemm(const uint32_t* __restrict__ A16, const uint32_t* __restrict__ W16,
        const float* __restrict__ bias, const float* __restrict__ dis,
        uint32_t* __restrict__ out16, int M)
{
    constexpr int NT = BN / 16;
    __shared__ __align__(16) uint32_t sA[4][128 * 8];
    __shared__ __align__(16) uint32_t sW[4][BN * 8];

    const int tid  = threadIdx.x;
    const int wid  = tid >> 5, lane = tid & 31;
    const int g    = lane >> 2, t = lane & 3;
    const int wm   = wid & 3, wn = wid >> 2;
    const int row0 = blockIdx.x * 128;

    const uint32_t sAb = sm32(sA);
    const uint32_t sWb = sm32(sW);
    constexpr uint32_t A_P = 128 * 8 * 4;
    constexpr uint32_t W_P = BN * 8 * 4;

    float acc[2][NT][4];
#pragma unroll
    for (int i = 0; i < 2; i++)
#pragma unroll
        for (int j = 0; j < NT; j++)
#pragma unroll
            for (int q = 0; q < 4; q++) acc[i][j][q] = 0.f;

    auto issue = [&](int kt, int buf) {
        int r = tid >> 1, h = tid & 1;
        int gr = row0 + r; if (gr >= M) gr = M - 1;
        uint32_t off = (uint32_t)(r * 8 + h * 4) * 4u;
        cpa16(sAb + (uint32_t)buf * A_P + off, A16 + (size_t)gr * 64 + kt * 8 + h * 4);
        if (tid < BN * 2) {
            cpa16(sWb + (uint32_t)buf * W_P + off, W16 + r * 64 + kt * 8 + h * 4);
        }
        asm volatile("cp.async.commit_group;" ::: "memory");
    };

    issue(0, 0);
    issue(1, 1);
    issue(2, 2);
    for (int kt = 0; kt < 8; kt++) {
        // ensure group kt is complete
        if (kt < 6) {
            asm volatile("cp.async.wait_group 2;" ::: "memory");
        } else if (kt == 6) {
            asm volatile("cp.async.wait_group 1;" ::: "memory");
        } else {
            asm volatile("cp.async.wait_group 0;" ::: "memory");
        }
        __syncthreads();          // all warps done reading buffer (kt-1)%4; data visible
        if (kt < 5) issue(kt + 3, (kt + 3) & 3);

        const uint32_t* pA = sA[kt & 3];
        const uint32_t* pW = sW[kt & 3];

        uint32_t a[2][4];
#pragma unroll
        for (int mt = 0; mt < 2; mt++) {
            int r0 = wm * 32 + mt * 16 + g;
            uint2 v;
            v = *reinterpret_cast<const uint2*>(&pA[r0 * 8 + t * 2]);
            a[mt][0] = v.x; a[mt][2] = v.y;
            v = *reinterpret_cast<const uint2*>(&pA[(r0 + 8) * 8 + t * 2]);
            a[mt][1] = v.x; a[mt][3] = v.y;
        }
#pragma unroll
        for (int nt = 0; nt < NT; nt++) {
            int rn = wn * (NT * 8) + nt * 8 + g;
            uint2 bw = *reinterpret_cast<const uint2*>(&pW[rn * 8 + t * 2]);
#pragma unroll
            for (int mt = 0; mt < 2; mt++) {
                MMA_F16(acc[mt][nt], a[mt], bw);
            }
        }
    }

    // ---- epilogue: v = (acc + bias) * dis ----
#pragma unroll
    for (int mt = 0; mt < 2; mt++) {
        int r0 = row0 + wm * 32 + mt * 16 + g;
        int r1 = r0 + 8;
        bool ok0 = r0 < M, ok1 = r1 < M;
        float sc0 = (SCALE && ok0) ? dis[r0] : 1.0f;
        float sc1 = (SCALE && ok1) ? dis[r1] : 1.0f;
#pragma unroll
        for (int nt = 0; nt < NT; nt++) {
            int c = wn * (NT * 8) + nt * 8 + 2 * t;
            float b0 = 0.f, b1 = 0.f;
            if (BIAS) {
                float2 bb = *reinterpret_cast<const float2*>(&bias[c]);
                b0 = bb.x; b1 = bb.y;
            }
            float v00 = (acc[mt][nt][0] + b0) * sc0;
            float v01 = (acc[mt][nt][1] + b1) * sc0;
            float v10 = (acc[mt][nt][2] + b0) * sc1;
            float v11 = (acc[mt][nt][3] + b1) * sc1;
            if (ok0) out16[(size_t)r0 * (BN / 2) + (c >> 1)] = packh2(v00, v01);
            if (ok1) out16[(size_t)r1 * (BN / 2) + (c >> 1)] = packh2(v10, v11);
        }
    }
}

// ---------------------------------------------------------------- aggregation
template <int COLS, bool RELU>
__global__ void k_agg(const uint32_t* __restrict__ tb16, const int* __restrict__ rowptr,
                      const int* __restrict__ esrc, const float* __restrict__ dis,
                      const float* __restrict__ bias, uint32_t* __restrict__ o16,
                      const int* __restrict__ batch, float* __restrict__ dout, int n) {
    const int warp = (blockIdx.x * blockDim.x + threadIdx.x) >> 5;
    const int lane = threadIdx.x & 31;
    if (warp >= n) return;
    const int beg = __ldg(&rowptr[warp]);
    const int end = __ldg(&rowptr[warp + 1]);

    if constexpr (COLS == 128) {
        uint2 sv = *reinterpret_cast<const uint2*>(&tb16[(size_t)warp * 64 + lane * 2]);
        float2 a0 = unph2(sv.x), a1 = unph2(sv.y);
        float4 acc = make_float4(a0.x, a0.y, a1.x, a1.y);
        int e = beg;
        for (; e + 8 <= end; e += 8) {
            int s[8];
#pragma unroll
            for (int u = 0; u < 8; u++) s[u] = __ldg(&esrc[e + u]);
            uint2 v[8];
#pragma unroll
            for (int u = 0; u < 8; u++)
                v[u] = *reinterpret_cast<const uint2*>(&tb16[(size_t)s[u] * 64 + lane * 2]);
#pragma unroll
            for (int u = 0; u < 8; u++) {
                float2 f0 = unph2(v[u].x), f1 = unph2(v[u].y);
                acc.x += f0.x; acc.y += f0.y; acc.z += f1.x; acc.w += f1.y;
            }
        }
        for (; e < end; e++) {
            int s = __ldg(&esrc[e]);
            uint2 v = *reinterpret_cast<const uint2*>(&tb16[(size_t)s * 64 + lane * 2]);
            float2 f0 = unph2(v.x), f1 = unph2(v.y);
            acc.x += f0.x; acc.y += f0.y; acc.z += f1.x; acc.w += f1.y;
        }
        float d = dis[warp];
        float4 b = *reinterpret_cast<const float4*>(&bias[lane * 4]);
        float4 r;
        r.x = fmaf(acc.x, d, b.x);
        r.y = fmaf(acc.y, d, b.y);
        r.z = fmaf(acc.z, d, b.z);
        r.w = fmaf(acc.w, d, b.w);
        if (RELU) {
            r.x = fmaxf(r.x, 0.f); r.y = fmaxf(r.y, 0.f);
            r.z = fmaxf(r.z, 0.f); r.w = fmaxf(r.w, 0.f);
        }
        int m0 = lane * 2;
        o16[(size_t)warp * 64 + widx(m0)]     = packh2(r.x, r.y);
        o16[(size_t)warp * 64 + widx(m0 + 1)] = packh2(r.z, r.w);
    } else {  // COLS == 64: fused pool
        float2 acc = unph2(tb16[(size_t)warp * 32 + lane]);
        int e = beg;
        for (; e + 8 <= end; e += 8) {
            int s[8];
#pragma unroll
            for (int u = 0; u < 8; u++) s[u] = __ldg(&esrc[e + u]);
            uint32_t v[8];
#pragma unroll
            for (int u = 0; u < 8; u++) v[u] = tb16[(size_t)s[u] * 32 + lane];
#pragma unroll
            for (int u = 0; u < 8; u++) {
                float2 f = unph2(v[u]);
                acc.x += f.x; acc.y += f.y;
            }
        }
        for (; e < end; e++) {
            int s = __ldg(&esrc[e]);
            float2 f = unph2(tb16[(size_t)s * 32 + lane]);
            acc.x += f.x; acc.y += f.y;
        }
        float d = dis[warp];
        float2 b = *reinterpret_cast<const float2*>(&bias[lane * 2]);
        float rx = fmaf(acc.x, d, b.x);
        float ry = fmaf(acc.y, d, b.y);
        int gidx = __ldg(&batch[warp]);
        float* a = &dout[(size_t)gidx * 64 + lane * 2];
        asm volatile("red.global.add.v2.f32 [%0], {%1,%2};"
                     :: "l"(a), "f"(rx), "f"(ry) : "memory");
    }
}

// ---------------------------------------------------------------- launch
extern "C" void kernel_launch(void* const* d_in, const int* in_sizes, int n_in,
                              void* d_out, int out_size) {
    const float* x     = (const float*)d_in[0];
    const int*   ei    = (const int*)  d_in[1];
    const int*   batch = (const int*)  d_in[2];
    const float* W_emb = (const float*)d_in[3];
    const float* b_emb = (const float*)d_in[4];
    const float* W1    = (const float*)d_in[5];
    const float* b1    = (const float*)d_in[6];
    const float* W2    = (const float*)d_in[7];
    const float* b2    = (const float*)d_in[8];
    const float* W3    = (const float*)d_in[9];
    const float* b3    = (const float*)d_in[10];

    const int n = in_sizes[2];
    const int e = in_sizes[1] / 2;
    const int* src = ei;
    const int* dst = ei + e;

    float *dis, *bc;
    int *rowptr, *esrc;
    uint32_t *t16, *a16, *b16, *w16;
    cudaGetSymbolAddress((void**)&dis,    g_dis);
    cudaGetSymbolAddress((void**)&bc,     g_bc);
    cudaGetSymbolAddress((void**)&rowptr, g_rowptr);
    cudaGetSymbolAddress((void**)&esrc,   g_esrc);
    cudaGetSymbolAddress((void**)&t16,    g_t16);
    cudaGetSymbolAddress((void**)&a16,    g_a16);
    cudaGetSymbolAddress((void**)&b16,    g_b16);
    cudaGetSymbolAddress((void**)&w16,    g_w16);

    auto cdiv = [](long long a, long long b) { return (int)((a + b - 1) / b); };

    // 0: fused prep (CSR + dis + weight images + Wc/bc + xconv + zero d_out)
    k_prep<<<PREP_BLOCKS, PREP_THREADS>>>(src, dst, e, n, (float*)d_out, out_size / 4,
                                          x, W_emb, W1, W2, W3, b_emb, a16);
    // 1: layer-1 GEMM (folded embedding)  t16 = fp16((x@Wc + bc) * dis)
    k_mgemm<128, true, true><<<cdiv(n, 128), 256>>>(
        a16, w16 + 0 * 8192, bc, dis, t16, n);
    // 2: layer-1 agg -> fp16
    k_agg<128, true><<<cdiv(n, 8), 256>>>(t16, rowptr, esrc, dis, b1, b16,
                                          nullptr, nullptr, n);
    // 3: layer-2 GEMM
    k_mgemm<128, true, false><<<cdiv(n, 128), 256>>>(
        b16, w16 + 2 * 8192, nullptr, dis, t16, n);
    // 4: layer-2 agg
    k_agg<128, true><<<cdiv(n, 8), 256>>>(t16, rowptr, esrc, dis, b2, a16,
                                          nullptr, nullptr, n);
    // 5: layer-3 GEMM (BN = 64)
    k_mgemm<64, true, false><<<cdiv(n, 128), 256>>>(
        a16, w16 + 3 * 8192, nullptr, dis, t16, n);
    // 6: layer-3 agg + fused pool
    k_agg<64, false><<<cdiv(n, 8), 256>>>(t16, rowptr, esrc, dis, b3, nullptr,
                                          batch, (float*)d_out, n);
}